// round 1
// baseline (speedup 1.0000x reference)
#include <cuda_runtime.h>

#define N_  4
#define C_  128
#define HW_ 4096
#define W_  64

// Scratch: per-(n,k) packed corner indices and coefficients (valid folded in).
__device__ int4   g_idx[N_ * HW_];
__device__ float4 g_cf [N_ * HW_];

// ---------------------------------------------------------------------------
// Kernel 1: compute interpolation taps for every (n, k) position.
// valid[k] = position in-range for ALL n grids (matches .all(0) in reference).
// ---------------------------------------------------------------------------
__global__ void prep_kernel(const float* __restrict__ grid) {
    int k = blockIdx.x * blockDim.x + threadIdx.x;
    if (k >= HW_) return;

    float gx[N_], gy[N_];
    bool valid = true;
    const float2* g2 = (const float2*)grid;  // (N, HW, 2) interleaved
#pragma unroll
    for (int n = 0; n < N_; ++n) {
        float2 g = g2[n * HW_ + k];
        gx[n] = g.x;
        gy[n] = g.y;
        valid = valid && (g.x >= -0.001f) && (g.x <= 63.001f)
                      && (g.y >= -0.001f) && (g.y <= 63.001f);
    }
    float vf = valid ? 1.0f : 0.0f;

#pragma unroll
    for (int n = 0; n < N_; ++n) {
        float x = fminf(fmaxf(gx[n], 0.001f), 62.999f);
        float y = fminf(fmaxf(gy[n], 0.001f), 62.999f);
        float flx = floorf(x);
        float fly = floorf(y);
        int   ix  = (int)flx;
        int   iy  = (int)fly;
        float fx  = x - flx;
        float fy  = y - fly;
        int c0 = ix * W_ + iy;
        // offs = [[0,0],[0,1],[1,0],[1,1]]
        g_idx[n * HW_ + k] = make_int4(c0, c0 + 1, c0 + W_, c0 + W_ + 1);
        // coeffs = outer([1-fx, fx], [fx, fy])  (faithful to source, non-standard)
        g_cf[n * HW_ + k] = make_float4((1.0f - fx) * fx * vf,
                                        (1.0f - fx) * fy * vf,
                                        fx * fx * vf,
                                        fx * fy * vf);
    }
}

// ---------------------------------------------------------------------------
// Kernel 2: one block per (n, c). Stage x[n,c,:] (16 KB) into smem, then
// gather 4 taps per output position. Output writes fully coalesced.
// ---------------------------------------------------------------------------
__global__ __launch_bounds__(256, 4)
void gather_kernel(const float* __restrict__ x, float* __restrict__ out) {
    __shared__ float sx[HW_];

    int nc = blockIdx.x;        // 0 .. N_*C_-1
    int n  = nc >> 7;           // / C_

    // Stage the row (coalesced float4 loads).
    const float4* xr = (const float4*)(x + (size_t)nc * HW_);
    float4* s4 = (float4*)sx;
#pragma unroll
    for (int i = threadIdx.x; i < HW_ / 4; i += 256) {
        s4[i] = xr[i];
    }
    __syncthreads();

    const int4*   idx = g_idx + n * HW_;
    const float4* cf  = g_cf  + n * HW_;
    float* o = out + (size_t)nc * HW_;

#pragma unroll 4
    for (int k = threadIdx.x; k < HW_; k += 256) {
        int4   id = idx[k];
        float4 w  = cf[k];
        float v = w.x * sx[id.x]
                + w.y * sx[id.y]
                + w.z * sx[id.z]
                + w.w * sx[id.w];
        o[k] = v;
    }
}

extern "C" void kernel_launch(void* const* d_in, const int* in_sizes, int n_in,
                              void* d_out, int out_size) {
    const float* x    = (const float*)d_in[0];   // (4, 128, 4096) f32
    const float* grid = (const float*)d_in[1];   // (4, 64, 64, 2) f32
    float* out = (float*)d_out;                  // (4, 128, 4096) f32

    prep_kernel<<<(HW_ + 255) / 256, 256>>>(grid);
    gather_kernel<<<N_ * C_, 256>>>(x, out);
}

// round 2
// speedup vs baseline: 1.1800x; 1.1800x over previous
#include <cuda_runtime.h>

#define N_  4
#define C_  128
#define HW_ 4096
#define W_  64

// Per-(n,k) tap data: base corner index c0, and (fx, fy) with validity folded
// in (invalid -> fx=fy=0 -> all four bilinear coeffs are exactly 0).
__device__ int    g_c0[N_ * HW_];
__device__ float2 g_f [N_ * HW_];

// ---------------------------------------------------------------------------
// Kernel 1: compute taps per (n, k). valid[k] requires in-range in ALL n grids.
// Corners are (c0, c0+1, c0+64, c0+65); coeffs = outer([1-fx, fx], [fx, fy]).
// ---------------------------------------------------------------------------
__global__ void prep_kernel(const float* __restrict__ grid) {
    int k = blockIdx.x * blockDim.x + threadIdx.x;
    if (k >= HW_) return;

    const float2* g2 = (const float2*)grid;  // (N, HW, 2)
    float gx[N_], gy[N_];
    bool valid = true;
#pragma unroll
    for (int n = 0; n < N_; ++n) {
        float2 g = g2[n * HW_ + k];
        gx[n] = g.x;
        gy[n] = g.y;
        valid = valid && (g.x >= -0.001f) && (g.x <= 63.001f)
                      && (g.y >= -0.001f) && (g.y <= 63.001f);
    }

#pragma unroll
    for (int n = 0; n < N_; ++n) {
        float xx = fminf(fmaxf(gx[n], 0.001f), 62.999f);
        float yy = fminf(fmaxf(gy[n], 0.001f), 62.999f);
        float flx = floorf(xx);
        float fly = floorf(yy);
        float fx  = xx - flx;
        float fy  = yy - fly;
        g_c0[n * HW_ + k] = (int)flx * W_ + (int)fly;
        g_f [n * HW_ + k] = valid ? make_float2(fx, fy) : make_float2(0.f, 0.f);
    }
}

// ---------------------------------------------------------------------------
// Kernel 2: one block per (n, c). Stage x[n,c,:] as 8B-aligned PAIRS in smem
// so each corner pair (j, j+1) is a single LDS.64. Each thread produces 4
// consecutive outputs per group (float4 store), 4 groups, fully unrolled so
// ptxas can front-batch the tap LDGs (MLP).
// ---------------------------------------------------------------------------
__global__ __launch_bounds__(256, 4)
void gather_kernel(const float* __restrict__ x, float* __restrict__ out) {
    __shared__ float2 sp[HW_];   // 32 KB: sp[j] = (x[j], x[j+1])

    int nc = blockIdx.x;         // 0 .. 511
    int n  = nc >> 7;            // nc / C_

    const float* xr = x + (size_t)nc * HW_;
#pragma unroll
    for (int j = threadIdx.x; j < HW_; j += 256) {
        float a = __ldg(xr + j);
        float b = (j + 1 < HW_) ? __ldg(xr + j + 1) : 0.f;  // sp[4095].y never read
        sp[j] = make_float2(a, b);
    }
    __syncthreads();

    const int4*   c04 = (const int4*)  (g_c0 + n * HW_);
    const float4* f4  = (const float4*)(g_f  + n * HW_);
    float4* o4 = (float4*)(out + (size_t)nc * HW_);

#pragma unroll
    for (int g = 0; g < 4; ++g) {
        int base = g * 256 + threadIdx.x;    // float4 index (coalesced)
        int4   c  = c04[base];
        float4 fA = f4[2 * base];            // (fx0,fy0, fx1,fy1)
        float4 fB = f4[2 * base + 1];        // (fx2,fy2, fx3,fy3)

        float2 a0 = sp[c.x], b0 = sp[c.x + 64];
        float2 a1 = sp[c.y], b1 = sp[c.y + 64];
        float2 a2 = sp[c.z], b2 = sp[c.z + 64];
        float2 a3 = sp[c.w], b3 = sp[c.w + 64];

        float4 r;
        {
            float u = fA.x * a0.x + fA.y * a0.y;
            float v = fA.x * b0.x + fA.y * b0.y;
            r.x = (1.0f - fA.x) * u + fA.x * v;
        }
        {
            float u = fA.z * a1.x + fA.w * a1.y;
            float v = fA.z * b1.x + fA.w * b1.y;
            r.y = (1.0f - fA.z) * u + fA.z * v;
        }
        {
            float u = fB.x * a2.x + fB.y * a2.y;
            float v = fB.x * b2.x + fB.y * b2.y;
            r.z = (1.0f - fB.x) * u + fB.x * v;
        }
        {
            float u = fB.z * a3.x + fB.w * a3.y;
            float v = fB.z * b3.x + fB.w * b3.y;
            r.w = (1.0f - fB.z) * u + fB.z * v;
        }
        o4[base] = r;
    }
}

extern "C" void kernel_launch(void* const* d_in, const int* in_sizes, int n_in,
                              void* d_out, int out_size) {
    const float* x    = (const float*)d_in[0];   // (4, 128, 4096) f32
    const float* grid = (const float*)d_in[1];   // (4, 64, 64, 2) f32
    float* out = (float*)d_out;                  // (4, 128, 4096) f32

    prep_kernel<<<(HW_ + 255) / 256, 256>>>(grid);
    gather_kernel<<<N_ * C_, 256>>>(x, out);
}